// round 2
// baseline (speedup 1.0000x reference)
#include <cuda_runtime.h>
#include <cuda_bf16.h>

#define HH      512          // hidden size (floats)
#define H2      256          // hidden size in float2
#define REF_S   256
#define TAR_S   512
#define NB      8            // batch
#define ND      32           // ref docs
#define NREFBLK (NB*ND)      // 256
#define NLAB    5

// flat fp32 output layout (reference tuple order, masks as 0/1 floats)
#define O_TAR_AUG       0        // [8,5,512]   = 20480
#define O_TAR_AUG_MASK  20480    // [8,5]       = 40
#define O_REF_AUG       20520    // [8,32,5,512]= 655360
#define O_REF_AUG_MASK  675880   // [8,32,5]    = 1280
#define O_TARPAPER      677160   // [8,512]     = 4096
#define O_TAR_MASK2     681256   // [8]         = 8
#define O_REFPAPER      681264   // [8,32,512]  = 131072
#define O_REF_MASK2     812336   // [8,32]      = 256
// total 812592

__global__ __launch_bounds__(256, 2)
void em_encoder_kernel(const float* __restrict__ tar_state,
                       const int*   __restrict__ tar_func,
                       const float* __restrict__ ref_state,
                       const int*   __restrict__ ref_func,
                       float*       __restrict__ out)
{
    __shared__ int            sfunc[TAR_S];
    __shared__ unsigned short slist[NLAB][TAR_S];
    __shared__ int            scnt[NLAB];

    const int bid  = blockIdx.x;
    const int t    = threadIdx.x;      // 0..255, owns float2 column t
    const bool is_ref = (bid < NREFBLK);
    const int S = is_ref ? REF_S : TAR_S;

    const float2* st;
    const int*    fn;
    if (is_ref) {
        st = reinterpret_cast<const float2*>(ref_state) + (size_t)bid * REF_S * H2;
        fn = ref_func + bid * REF_S;
    } else {
        const int b = bid - NREFBLK;
        st = reinterpret_cast<const float2*>(tar_state) + (size_t)b * TAR_S * H2;
        fn = tar_func + b * TAR_S;
    }

    // stage func into shared
    for (int s = t; s < S; s += 256) sfunc[s] = fn[s];
    __syncthreads();

    // Deterministic warp-ballot compaction: warp w builds the index list of
    // sentences with label w+1 (ascending s order — same every run).
    const int wid = t >> 5, lane = t & 31;
    if (wid < NLAB) {
        const int l = wid + 1;
        int base = 0;
        for (int s0 = 0; s0 < S; s0 += 32) {
            const int s = s0 + lane;
            const int f = sfunc[s];
            const unsigned m = __ballot_sync(0xffffffffu, f == l);
            if (f == l)
                slist[wid][base + __popc(m & ((1u << lane) - 1u))] = (unsigned short)s;
            base += __popc(m);
        }
        if (lane == 0) scnt[wid] = base;
    }
    __syncthreads();

    // Hot loop: per label, gather-sum the rows in its list.
    float2 acc[NLAB];
    float2 tot = make_float2(0.f, 0.f);
    int    cnt[NLAB];

    #pragma unroll
    for (int l = 0; l < NLAB; l++) {
        const int n = scnt[l];
        cnt[l] = n;
        float2 a = make_float2(0.f, 0.f);
        int j = 0;
        for (; j + 8 <= n; j += 8) {
            // 8 independent LDG.64 in flight per warp per iteration
            float2 v0 = st[(size_t)slist[l][j+0] * H2 + t];
            float2 v1 = st[(size_t)slist[l][j+1] * H2 + t];
            float2 v2 = st[(size_t)slist[l][j+2] * H2 + t];
            float2 v3 = st[(size_t)slist[l][j+3] * H2 + t];
            float2 v4 = st[(size_t)slist[l][j+4] * H2 + t];
            float2 v5 = st[(size_t)slist[l][j+5] * H2 + t];
            float2 v6 = st[(size_t)slist[l][j+6] * H2 + t];
            float2 v7 = st[(size_t)slist[l][j+7] * H2 + t];
            a.x += ((v0.x + v1.x) + (v2.x + v3.x)) + ((v4.x + v5.x) + (v6.x + v7.x));
            a.y += ((v0.y + v1.y) + (v2.y + v3.y)) + ((v4.y + v5.y) + (v6.y + v7.y));
        }
        for (; j < n; j++) {
            float2 v = st[(size_t)slist[l][j] * H2 + t];
            a.x += v.x; a.y += v.y;
        }
        acc[l] = a;
        tot.x += a.x; tot.y += a.y;     // masked (func!=0) sum == sum over labels 1..5
    }
    const int ctot = cnt[0] + cnt[1] + cnt[2] + cnt[3] + cnt[4];

    // epilogue
    if (is_ref) {
        float* aug = out + O_REF_AUG + (size_t)bid * NLAB * HH;
        #pragma unroll
        for (int l = 0; l < NLAB; l++) {
            const float inv = 1.f / (cnt[l] > 0 ? (float)cnt[l] : 1e11f);
            reinterpret_cast<float2*>(aug + l * HH)[t] =
                make_float2(acc[l].x * inv, acc[l].y * inv);
        }
        const float invt = 1.f / (ctot > 0 ? (float)ctot : 1e11f);
        reinterpret_cast<float2*>(out + O_REFPAPER + (size_t)bid * HH)[t] =
            make_float2(tot.x * invt, tot.y * invt);
        if (t < NLAB) out[O_REF_AUG_MASK + bid * NLAB + t] = (scnt[t] > 0) ? 1.f : 0.f;
        if (t == 0)   out[O_REF_MASK2 + bid] = (ctot > 0) ? 1.f : 0.f;
    } else {
        const int b = bid - NREFBLK;
        float* aug = out + O_TAR_AUG + (size_t)b * NLAB * HH;
        #pragma unroll
        for (int l = 0; l < NLAB; l++) {
            const float inv = 1.f / (cnt[l] > 0 ? (float)cnt[l] : 1e11f);
            reinterpret_cast<float2*>(aug + l * HH)[t] =
                make_float2(acc[l].x * inv, acc[l].y * inv);
        }
        const float invt = 1.f / (ctot > 0 ? (float)ctot : 1e11f);
        reinterpret_cast<float2*>(out + O_TARPAPER + (size_t)b * HH)[t] =
            make_float2(tot.x * invt, tot.y * invt);
        if (t < NLAB) out[O_TAR_AUG_MASK + b * NLAB + t] = (scnt[t] > 0) ? 1.f : 0.f;
        if (t == 0)   out[O_TAR_MASK2 + b] = (ctot > 0) ? 1.f : 0.f;
    }
}

extern "C" void kernel_launch(void* const* d_in, const int* in_sizes, int n_in,
                              void* d_out, int out_size) {
    const float* tar_state = (const float*)d_in[0];
    const int*   tar_func  = (const int*)  d_in[1];
    const float* ref_state = (const float*)d_in[2];
    const int*   ref_func  = (const int*)  d_in[3];
    float* out = (float*)d_out;

    em_encoder_kernel<<<NREFBLK + NB, 256>>>(tar_state, tar_func,
                                             ref_state, ref_func, out);
}